// round 7
// baseline (speedup 1.0000x reference)
#include <cuda_runtime.h>

#define T_LEN  1024
#define NSTEP  1023
#define B_SZ   8192

typedef unsigned long long ull;

// scratch: time-major inputs + c_t buffer
__device__ int   g_act_t[T_LEN * B_SZ];            // [t][b]
__device__ float g_rew_t[T_LEN * B_SZ];            // [t][b]
__device__ float g_c[(size_t)B_SZ * NSTEP * 4];    // [b][t][4]

// ---------------- packed f32x2 helpers ----------------
__device__ __forceinline__ void ffma2(ull& d, ull a, ull b) {
    asm("fma.rn.f32x2 %0, %1, %2, %0;" : "+l"(d) : "l"(a), "l"(b));
}
__device__ __forceinline__ ull mul2(ull a, ull b) {
    ull r; asm("mul.rn.f32x2 %0, %1, %2;" : "=l"(r) : "l"(a), "l"(b)); return r;
}
__device__ __forceinline__ ull pack2(float x, float y) {
    ull r; asm("mov.b64 %0, {%1, %2};" : "=l"(r) : "f"(x), "f"(y)); return r;
}
__device__ __forceinline__ float2 unpack2(ull v) {
    float2 r; asm("mov.b64 {%0, %1}, %2;" : "=f"(r.x), "=f"(r.y) : "l"(v)); return r;
}
// input pre-scaled by 2*log2(e): tanh = 1 - 2/(2^x' + 1)   (~1e-6 abs err)
__device__ __forceinline__ float tanh_pre(float xs) {
    float e, r;
    asm("ex2.approx.f32 %0, %1;" : "=f"(e) : "f"(xs));
    asm("rcp.approx.f32 %0, %1;" : "=f"(r) : "f"(e + 1.0f));
    return fmaf(-2.0f, r, 1.0f);
}
#define TANH_SC 2.8853900817779268f   // 2*log2(e)

// ---------------- transpose [B][T] -> [T][B] ----------------
__global__ void __launch_bounds__(256)
transpose_kernel(const int* __restrict__ act, const float* __restrict__ rew) {
    __shared__ unsigned tile[32][33];
    const int tt = blockIdx.x * 32, tb = blockIdx.y * 32;
    const unsigned* src = (blockIdx.z == 0) ? (const unsigned*)act : (const unsigned*)rew;
    unsigned*       dst = (blockIdx.z == 0) ? (unsigned*)g_act_t  : (unsigned*)g_rew_t;
    const int tx = threadIdx.x, ty = threadIdx.y;
    #pragma unroll
    for (int i = 0; i < 32; i += 8)
        tile[ty + i][tx] = src[(long long)(tb + ty + i) * T_LEN + tt + tx];
    __syncthreads();
    #pragma unroll
    for (int i = 0; i < 32; i += 8)
        dst[(long long)(tt + ty + i) * B_SZ + tb + tx] = tile[tx][ty + i];
}

// ---------------- main recurrent kernel ----------------
// grid = 128 CTAs x 128 thr (4 warps -> 4 SMSPs). Warps 0,1: reward module;
// warps 2,3: action module. ONE LANE = ONE ELEMENT: the full 32-dim module
// state lives in 16 f32x2 registers. No shuffles, no syncs, no cross-lane
// traffic. All weight reads are warp-uniform SMEM broadcasts (conflict-free).
// 512 total warps -> one warp per SMSP chip-wide; each free-runs its 1023 steps.
__global__ void __launch_bounds__(128)
memann_mod(const float* __restrict__ w_r1, const float* __restrict__ b_r1,
           const float* __restrict__ w_r2, const float* __restrict__ b_r2,
           const float* __restrict__ w_a1, const float* __restrict__ b_a1,
           const float* __restrict__ w_a2, const float* __restrict__ b_a2,
           float*       __restrict__ out)
{
    // prescaled first-layer weights, [row][pair] (pair p = state dims 2p,2p+1)
    __shared__ __align__(16) ull  w1r[32][16];
    __shared__ __align__(16) ull  w1a[32][16];
    __shared__ __align__(16) ull  bwr[32];        // {b_r1', w_r1[.,0]'}
    __shared__ __align__(16) ull  w2r[16];        // w_r2 pairs (unscaled)
    __shared__ __align__(16) ull  w2a[4][16];     // w_a2 pairs (unscaled)
    __shared__ __align__(16) float colbf[4][32];  // (w_a1[r][a]+b_a1[r])'
    __shared__ float sc[5];                        // b_r2, b_a2[0..3]

    const int tid = threadIdx.x;

    // ---- one-time staging ----
    #pragma unroll
    for (int k = 0; k < 4; k++) {
        const int idx = tid * 4 + k;              // 512 pairs
        const int row = idx >> 4, p = idx & 15;
        w1r[row][p] = pack2(w_r1[row * 33 + 1 + 2 * p] * TANH_SC,
                            w_r1[row * 33 + 2 + 2 * p] * TANH_SC);
        w1a[row][p] = pack2(w_a1[row * 36 + 4 + 2 * p] * TANH_SC,
                            w_a1[row * 36 + 5 + 2 * p] * TANH_SC);
    }
    if (tid < 32)
        bwr[tid] = pack2(b_r1[tid] * TANH_SC, w_r1[tid * 33] * TANH_SC);
    if (tid >= 32 && tid < 48)
        w2r[tid - 32] = pack2(w_r2[2 * (tid - 32)], w_r2[2 * (tid - 32) + 1]);
    if (tid >= 64 && tid < 128) {
        const int k = (tid - 64) >> 4, p = (tid - 64) & 15;
        w2a[k][p] = pack2(w_a2[k * 32 + 2 * p], w_a2[k * 32 + 2 * p + 1]);
    }
    {
        const int a = tid >> 5, row = tid & 31;
        colbf[a][row] = (w_a1[row * 36 + a] + b_a1[row]) * TANH_SC;
    }
    if (tid == 48) sc[0] = b_r2[0];
    if (tid >= 49 && tid < 53) sc[tid - 48] = b_a2[tid - 49];
    __syncthreads();

    const int lane = tid & 31, wid = tid >> 5;
    const bool is_reward = wid < 2;
    const long long b = (long long)blockIdx.x * 64 + (wid & 1) * 32 + lane;
    const int*   ap = g_act_t + b;
    const float* rp = g_rew_t + b;

    ull s[16];
    #pragma unroll
    for (int p = 0; p < 16; p++) s[p] = 0ull;

    if (is_reward) {
        // ================= reward module: full matvec in-lane =================
        const float br2 = sc[0];
        float q0 = 0.f, q1 = 0.f, q2 = 0.f, q3 = 0.f;
        float* op = out + (size_t)b * (NSTEP * 4);

        int   a_cur = ap[0];
        float r_cur = rp[0];
        for (int t = 0; t < NSTEP; t++) {
            const int   a_nxt = ap[(t + 1) * B_SZ];
            const float r_nxt = rp[(t + 1) * B_SZ];
            const ull   rv    = pack2(1.0f, r_cur);

            float sn[32];
            #pragma unroll
            for (int pass = 0; pass < 2; pass++) {       // 16 rows per pass
                ull acc[16];
                #pragma unroll
                for (int r2 = 0; r2 < 8; r2++) {
                    const ulonglong2 bw = *(const ulonglong2*)&bwr[pass * 16 + 2 * r2];
                    acc[2 * r2]     = mul2(bw.x, rv);     // {b', w0'*r}
                    acc[2 * r2 + 1] = mul2(bw.y, rv);
                }
                #pragma unroll
                for (int pp = 0; pp < 8; pp++) {
                    const ull s0 = s[2 * pp], s1 = s[2 * pp + 1];
                    #pragma unroll
                    for (int r = 0; r < 16; r++) {
                        const ulonglong2 w =
                            *(const ulonglong2*)&w1r[pass * 16 + r][2 * pp];
                        ffma2(acc[r], w.x, s0);
                        ffma2(acc[r], w.y, s1);
                    }
                }
                #pragma unroll
                for (int r = 0; r < 16; r++) {
                    const float2 u = unpack2(acc[r]);
                    sn[pass * 16 + r] = tanh_pre(u.x + u.y);
                }
            }
            #pragma unroll
            for (int p = 0; p < 16; p++) s[p] = pack2(sn[2 * p], sn[2 * p + 1]);

            // q_new = w_r2 . s + b_r2 (fully in-lane)
            ull qa = 0ull;
            #pragma unroll
            for (int pp = 0; pp < 8; pp++) {
                const ulonglong2 w = *(const ulonglong2*)&w2r[2 * pp];
                ffma2(qa, w.x, s[2 * pp]);
                ffma2(qa, w.y, s[2 * pp + 1]);
            }
            const float2 qf = unpack2(qa);
            const float q_new = qf.x + qf.y + br2;

            q0 = (a_cur == 0) ? q_new : q0 * 0.95f;
            q1 = (a_cur == 1) ? q_new : q1 * 0.95f;
            q2 = (a_cur == 2) ? q_new : q2 * 0.95f;
            q3 = (a_cur == 3) ? q_new : q3 * 0.95f;
            *(float4*)(op + (size_t)t * 4) = make_float4(q0, q1, q2, q3);

            a_cur = a_nxt; r_cur = r_nxt;
        }
    } else {
        // ================= action-history module =================
        const float ba0 = sc[1], ba1 = sc[2], ba2v = sc[3], ba3 = sc[4];
        float* cp = g_c + (size_t)b * (NSTEP * 4);

        int a_cur = ap[0];
        for (int t = 0; t < NSTEP; t++) {
            const int a_nxt = ap[(t + 1) * B_SZ];

            float sn[32];
            #pragma unroll
            for (int pass = 0; pass < 2; pass++) {
                ull acc[16];
                #pragma unroll
                for (int r = 0; r < 16; r++) acc[r] = 0ull;
                #pragma unroll
                for (int pp = 0; pp < 8; pp++) {
                    const ull s0 = s[2 * pp], s1 = s[2 * pp + 1];
                    #pragma unroll
                    for (int r = 0; r < 16; r++) {
                        const ulonglong2 w =
                            *(const ulonglong2*)&w1a[pass * 16 + r][2 * pp];
                        ffma2(acc[r], w.x, s0);
                        ffma2(acc[r], w.y, s1);
                    }
                }
                #pragma unroll
                for (int r4 = 0; r4 < 4; r4++) {
                    const float4 cb =
                        *(const float4*)&colbf[a_cur][pass * 16 + 4 * r4];
                    const float cbv[4] = {cb.x, cb.y, cb.z, cb.w};
                    #pragma unroll
                    for (int k = 0; k < 4; k++) {
                        const float2 u = unpack2(acc[r4 * 4 + k]);
                        sn[pass * 16 + r4 * 4 + k] = tanh_pre(u.x + u.y + cbv[k]);
                    }
                }
            }
            #pragma unroll
            for (int p = 0; p < 16; p++) s[p] = pack2(sn[2 * p], sn[2 * p + 1]);

            // c = W_a2 @ s + b_a2 (fully in-lane, 4 outputs)
            ull c0 = 0ull, c1 = 0ull, c2 = 0ull, c3 = 0ull;
            #pragma unroll
            for (int pp = 0; pp < 8; pp++) {
                const ulonglong2 wA = *(const ulonglong2*)&w2a[0][2 * pp];
                const ulonglong2 wB = *(const ulonglong2*)&w2a[1][2 * pp];
                const ulonglong2 wC = *(const ulonglong2*)&w2a[2][2 * pp];
                const ulonglong2 wD = *(const ulonglong2*)&w2a[3][2 * pp];
                ffma2(c0, wA.x, s[2 * pp]); ffma2(c0, wA.y, s[2 * pp + 1]);
                ffma2(c1, wB.x, s[2 * pp]); ffma2(c1, wB.y, s[2 * pp + 1]);
                ffma2(c2, wC.x, s[2 * pp]); ffma2(c2, wC.y, s[2 * pp + 1]);
                ffma2(c3, wD.x, s[2 * pp]); ffma2(c3, wD.y, s[2 * pp + 1]);
            }
            const float2 f0 = unpack2(c0), f1 = unpack2(c1);
            const float2 f2 = unpack2(c2), f3 = unpack2(c3);
            *(float4*)(cp + (size_t)t * 4) =
                make_float4(f0.x + f0.y + ba0, f1.x + f1.y + ba1,
                            f2.x + f2.y + ba2v, f3.x + f3.y + ba3);

            a_cur = a_nxt;
        }
    }
}

// ---------------- out += c ----------------
__global__ void __launch_bounds__(256)
add_kernel(float* __restrict__ out) {
    const size_t n4 = (size_t)B_SZ * NSTEP;
    float4* o = (float4*)out;
    const float4* c = (const float4*)g_c;
    for (size_t i = (size_t)blockIdx.x * 256 + threadIdx.x; i < n4;
         i += (size_t)gridDim.x * 256) {
        float4 a = o[i], b = c[i];
        a.x += b.x; a.y += b.y; a.z += b.z; a.w += b.w;
        o[i] = a;
    }
}

extern "C" void kernel_launch(void* const* d_in, const int* in_sizes, int n_in,
                              void* d_out, int out_size) {
    (void)in_sizes; (void)n_in; (void)out_size;
    transpose_kernel<<<dim3(T_LEN / 32, B_SZ / 32, 2), dim3(32, 8)>>>(
        (const int*)d_in[0], (const float*)d_in[1]);
    memann_mod<<<128, 128>>>(
        (const float*)d_in[2], (const float*)d_in[3],
        (const float*)d_in[4], (const float*)d_in[5],
        (const float*)d_in[6], (const float*)d_in[7],
        (const float*)d_in[8], (const float*)d_in[9],
        (float*)d_out);
    add_kernel<<<2048, 256>>>((float*)d_out);
}

// round 8
// speedup vs baseline: 60.7972x; 60.7972x over previous
#include <cuda_runtime.h>

#define T_LEN  1024
#define NSTEP  1023
#define B_SZ   8192

typedef unsigned long long ull;

// scratch: time-major inputs + c_t buffer
__device__ int   g_act_t[T_LEN * B_SZ];            // [t][b]
__device__ float g_rew_t[T_LEN * B_SZ];            // [t][b]
__device__ float g_c[(size_t)B_SZ * NSTEP * 4];    // [b][t][4]

// ---------------- packed f32x2 helpers ----------------
__device__ __forceinline__ void ffma2(ull& d, ull a, ull b) {
    asm("fma.rn.f32x2 %0, %1, %2, %0;" : "+l"(d) : "l"(a), "l"(b));
}
__device__ __forceinline__ ull mul2(ull a, ull b) {
    ull r; asm("mul.rn.f32x2 %0, %1, %2;" : "=l"(r) : "l"(a), "l"(b)); return r;
}
__device__ __forceinline__ ull add2(ull a, ull b) {
    ull r; asm("add.rn.f32x2 %0, %1, %2;" : "=l"(r) : "l"(a), "l"(b)); return r;
}
__device__ __forceinline__ ull pack2(float x, float y) {
    ull r; asm("mov.b64 %0, {%1, %2};" : "=l"(r) : "f"(x), "f"(y)); return r;
}
__device__ __forceinline__ float2 unpack2(ull v) {
    float2 r; asm("mov.b64 {%0, %1}, %2;" : "=f"(r.x), "=f"(r.y) : "l"(v)); return r;
}
__device__ __forceinline__ ull shflx64(ull v, int m) {
    return __shfl_xor_sync(0xFFFFFFFFu, v, m);
}
// input pre-scaled by 2*log2(e):  tanh = 1 - 2/(2^x' + 1)   (~1e-6 abs err)
__device__ __forceinline__ float tanh_pre(float xs) {
    float e, r;
    asm("ex2.approx.f32 %0, %1;" : "=f"(e) : "f"(xs));
    asm("rcp.approx.f32 %0, %1;" : "=f"(r) : "f"(e + 1.0f));
    return fmaf(-2.0f, r, 1.0f);
}
#define TANH_SC 2.8853900817779268f   // 2*log2(e)

// ---------------- transpose [B][T] -> [T][B] ----------------
__global__ void __launch_bounds__(256)
transpose_kernel(const int* __restrict__ act, const float* __restrict__ rew) {
    __shared__ unsigned tile[32][33];
    const int tt = blockIdx.x * 32, tb = blockIdx.y * 32;
    const unsigned* src = (blockIdx.z == 0) ? (const unsigned*)act : (const unsigned*)rew;
    unsigned*       dst = (blockIdx.z == 0) ? (unsigned*)g_act_t  : (unsigned*)g_rew_t;
    const int tx = threadIdx.x, ty = threadIdx.y;
    #pragma unroll
    for (int i = 0; i < 32; i += 8)
        tile[ty + i][tx] = src[(long long)(tb + ty + i) * T_LEN + tt + tx];
    __syncthreads();
    #pragma unroll
    for (int i = 0; i < 32; i += 8)
        dst[(long long)(tt + ty + i) * B_SZ + tb + tx] = tile[tx][ty + i];
}

// ---------------- main recurrent kernel (R3 geometry + prescaled weights) ----
// grid = 128 CTAs x 256 thr (8 warps). CTAs 0..63: reward module; 64..127: action.
// Warp handles 16 elements; lane pair (2e, 2e+1) shares element e: lane h owns
// weight rows / state dims [16h, 16h+16) in registers; halves swap via SHFL.
__global__ void __launch_bounds__(256, 1)
memann_mod(const float* __restrict__ w_r1, const float* __restrict__ b_r1,
           const float* __restrict__ w_r2, const float* __restrict__ b_r2,
           const float* __restrict__ w_a1, const float* __restrict__ b_a1,
           const float* __restrict__ w_a2, const float* __restrict__ b_a2,
           float*       __restrict__ out)
{
    // weight SMEM, interleaved so the 2 per-warp addresses are 16B apart
    __shared__ __align__(16) ulonglong2 wrk[16][8][2];  // [m][pp][h]: row h*16+m
    __shared__ __align__(16) ulonglong2 wak[16][8][2];
    __shared__ __align__(16) ull  bw1s[16][2];          // {b_r1', w_r1[.,0]'}
    __shared__ __align__(16) ull  wr2s[2][8];
    __shared__ __align__(16) ull  wa2s[4][2][8];
    __shared__ __align__(16) float colbf[4][2][16];     // (w_a1[r][a]+b_a1[r])'
    __shared__ float sc[5];                              // b_r2, b_a2[0..3]

    const int tid = threadIdx.x;
    const bool is_reward = blockIdx.x < 64;

    // ---- staging ----
    if (is_reward) {
        #pragma unroll
        for (int k = 0; k < 2; k++) {
            int idx = tid * 2 + k;                 // 512 ull
            int u2 = idx & 1, h = (idx >> 1) & 1, pp = (idx >> 2) & 7, m = idx >> 5;
            int row = h * 16 + m, u = 2 * pp + u2;
            ((ull*)&wrk[m][pp][h])[u2] =
                pack2(w_r1[row * 33 + 1 + 2 * u] * TANH_SC,
                      w_r1[row * 33 + 2 + 2 * u] * TANH_SC);
        }
        if (tid < 32) {
            int h = tid >> 4, m = tid & 15;
            int row = h * 16 + m;
            bw1s[m][h] = pack2(b_r1[row] * TANH_SC, w_r1[row * 33] * TANH_SC);
        }
        if (tid >= 64 && tid < 80) {
            int h = (tid - 64) >> 3, pp = (tid - 64) & 7;
            wr2s[h][pp] = pack2(w_r2[16 * h + 2 * pp], w_r2[16 * h + 2 * pp + 1]);
        }
        if (tid == 80) sc[0] = b_r2[0];
    } else {
        #pragma unroll
        for (int k = 0; k < 2; k++) {
            int idx = tid * 2 + k;
            int u2 = idx & 1, h = (idx >> 1) & 1, pp = (idx >> 2) & 7, m = idx >> 5;
            int row = h * 16 + m, u = 2 * pp + u2;
            ((ull*)&wak[m][pp][h])[u2] =
                pack2(w_a1[row * 36 + 4 + 2 * u] * TANH_SC,
                      w_a1[row * 36 + 5 + 2 * u] * TANH_SC);
        }
        if (tid < 128) {
            int a = tid >> 5, h = (tid >> 4) & 1, m = tid & 15;
            int row = h * 16 + m;
            colbf[a][h][m] = (w_a1[row * 36 + a] + b_a1[row]) * TANH_SC;
        }
        if (tid >= 128 && tid < 192) {
            int k2 = (tid - 128) >> 4, h = (tid - 128 >> 3) & 1, pp = (tid - 128) & 7;
            wa2s[k2][h][pp] = pack2(w_a2[k2 * 32 + 16 * h + 2 * pp],
                                    w_a2[k2 * 32 + 16 * h + 2 * pp + 1]);
        }
        if (tid >= 192 && tid < 196) sc[1 + tid - 192] = b_a2[tid - 192];
    }
    __syncthreads();

    const int lane = tid & 31, wid = tid >> 5;
    const int h  = lane & 1;
    const int el = lane >> 1;
    const int cta_mod = is_reward ? blockIdx.x : blockIdx.x - 64;
    const long long b = (long long)cta_mod * 128 + wid * 16 + el;
    const int*   ap = g_act_t + b;
    const float* rp = g_rew_t + b;

    ull sh[8];
    #pragma unroll
    for (int u = 0; u < 8; u++) sh[u] = 0ull;

    if (is_reward) {
        ull bi[16];                                   // 16 regs (prescaled pairs)
        #pragma unroll
        for (int m = 0; m < 16; m++) bi[m] = bw1s[m][h];
        ull w2r[8];
        #pragma unroll
        for (int pp = 0; pp < 8; pp++) w2r[pp] = wr2s[h][pp];
        const float br2 = sc[0];
        const int   kA = 2 * h, kB = 2 * h + 1;
        float qA = 0.f, qB = 0.f;
        float* op = out + (b * NSTEP) * 4 + 2 * h;

        int   a_cur = ap[0];
        float r_cur = rp[0];
        for (int t = 0; t < NSTEP; t++) {
            const int   a_nxt = ap[(t + 1) * B_SZ];
            const float r_nxt = rp[(t + 1) * B_SZ];
            ull xo[8];
            #pragma unroll
            for (int u = 0; u < 8; u++) xo[u] = shflx64(sh[u], 1);
            const ull rv = pack2(1.0f, r_cur);

            float sn[16];
            #pragma unroll
            for (int m4 = 0; m4 < 4; m4++) {
                ull acc[4];
                #pragma unroll
                for (int mm = 0; mm < 4; mm++)
                    acc[mm] = mul2(bi[m4 * 4 + mm], rv);   // {b', w0'*r}
                #pragma unroll
                for (int ppo = 0; ppo < 4; ppo++) {         // own half first
                    const int pp = h * 4 + ppo;
                    #pragma unroll
                    for (int mm = 0; mm < 4; mm++) {
                        ulonglong2 w = wrk[m4 * 4 + mm][pp][h];
                        ffma2(acc[mm], w.x, sh[2 * ppo]);
                        ffma2(acc[mm], w.y, sh[2 * ppo + 1]);
                    }
                }
                #pragma unroll
                for (int ppo = 0; ppo < 4; ppo++) {         // partner half
                    const int pq = (1 - h) * 4 + ppo;
                    #pragma unroll
                    for (int mm = 0; mm < 4; mm++) {
                        ulonglong2 w = wrk[m4 * 4 + mm][pq][h];
                        ffma2(acc[mm], w.x, xo[2 * ppo]);
                        ffma2(acc[mm], w.y, xo[2 * ppo + 1]);
                    }
                }
                #pragma unroll
                for (int mm = 0; mm < 4; mm++) {
                    float2 u = unpack2(acc[mm]);
                    sn[m4 * 4 + mm] = tanh_pre(u.x + u.y);
                }
            }
            #pragma unroll
            for (int u = 0; u < 8; u++) sh[u] = pack2(sn[2 * u], sn[2 * u + 1]);

            ull qa = 0ull;
            #pragma unroll
            for (int pp = 0; pp < 8; pp++) ffma2(qa, w2r[pp], sh[pp]);
            float2 qf = unpack2(qa);
            float qs = qf.x + qf.y;
            qs += __shfl_xor_sync(0xFFFFFFFFu, qs, 1);
            const float q_new = qs + br2;

            qA = (a_cur == kA) ? q_new : qA * 0.95f;
            qB = (a_cur == kB) ? q_new : qB * 0.95f;
            *(float2*)(op + (size_t)t * 4) = make_float2(qA, qB);

            a_cur = a_nxt; r_cur = r_nxt;
        }
    } else {
        ull w2a[4][8];
        #pragma unroll
        for (int k = 0; k < 4; k++)
            #pragma unroll
            for (int pp = 0; pp < 8; pp++) w2a[k][pp] = wa2s[k][h][pp];
        const float baA = h ? sc[3] : sc[1];
        const float baB = h ? sc[4] : sc[2];
        float* cp = g_c + (b * NSTEP) * 4 + 2 * h;

        int a_cur = ap[0];
        for (int t = 0; t < NSTEP; t++) {
            const int a_nxt = ap[(t + 1) * B_SZ];
            ull xo[8];
            #pragma unroll
            for (int u = 0; u < 8; u++) xo[u] = shflx64(sh[u], 1);

            float sn[16];
            #pragma unroll
            for (int m4 = 0; m4 < 4; m4++) {
                const float4 cb = *(const float4*)&colbf[a_cur][h][m4 * 4];
                ull acc[4];
                #pragma unroll
                for (int mm = 0; mm < 4; mm++) acc[mm] = 0ull;
                #pragma unroll
                for (int ppo = 0; ppo < 4; ppo++) {
                    const int pp = h * 4 + ppo;
                    #pragma unroll
                    for (int mm = 0; mm < 4; mm++) {
                        ulonglong2 w = wak[m4 * 4 + mm][pp][h];
                        ffma2(acc[mm], w.x, sh[2 * ppo]);
                        ffma2(acc[mm], w.y, sh[2 * ppo + 1]);
                    }
                }
                #pragma unroll
                for (int ppo = 0; ppo < 4; ppo++) {
                    const int pq = (1 - h) * 4 + ppo;
                    #pragma unroll
                    for (int mm = 0; mm < 4; mm++) {
                        ulonglong2 w = wak[m4 * 4 + mm][pq][h];
                        ffma2(acc[mm], w.x, xo[2 * ppo]);
                        ffma2(acc[mm], w.y, xo[2 * ppo + 1]);
                    }
                }
                const float cbv[4] = {cb.x, cb.y, cb.z, cb.w};
                #pragma unroll
                for (int mm = 0; mm < 4; mm++) {
                    float2 u = unpack2(acc[mm]);
                    sn[m4 * 4 + mm] = tanh_pre(u.x + u.y + cbv[mm]);
                }
            }
            #pragma unroll
            for (int u = 0; u < 8; u++) sh[u] = pack2(sn[2 * u], sn[2 * u + 1]);

            ull ca0 = 0ull, ca1 = 0ull, ca2 = 0ull, ca3 = 0ull;
            #pragma unroll
            for (int pp = 0; pp < 8; pp++) {
                ffma2(ca0, w2a[0][pp], sh[pp]);
                ffma2(ca1, w2a[1][pp], sh[pp]);
                ffma2(ca2, w2a[2][pp], sh[pp]);
                ffma2(ca3, w2a[3][pp], sh[pp]);
            }
            float2 f0 = unpack2(ca0), f1 = unpack2(ca1), f2 = unpack2(ca2), f3 = unpack2(ca3);
            ull v01 = pack2(f0.x + f0.y, f1.x + f1.y);
            ull v23 = pack2(f2.x + f2.y, f3.x + f3.y);
            v01 = add2(v01, shflx64(v01, 1));
            v23 = add2(v23, shflx64(v23, 1));
            const ull    vsel = h ? v23 : v01;
            const float2 vv   = unpack2(vsel);
            *(float2*)(cp + (size_t)t * 4) = make_float2(vv.x + baA, vv.y + baB);

            a_cur = a_nxt;
        }
    }
}

// ---------------- out += c ----------------
__global__ void __launch_bounds__(256)
add_kernel(float* __restrict__ out) {
    const size_t n4 = (size_t)B_SZ * NSTEP;
    float4* o = (float4*)out;
    const float4* c = (const float4*)g_c;
    for (size_t i = (size_t)blockIdx.x * 256 + threadIdx.x; i < n4;
         i += (size_t)gridDim.x * 256) {
        float4 a = o[i], b = c[i];
        a.x += b.x; a.y += b.y; a.z += b.z; a.w += b.w;
        o[i] = a;
    }
}

extern "C" void kernel_launch(void* const* d_in, const int* in_sizes, int n_in,
                              void* d_out, int out_size) {
    (void)in_sizes; (void)n_in; (void)out_size;
    transpose_kernel<<<dim3(T_LEN / 32, B_SZ / 32, 2), dim3(32, 8)>>>(
        (const int*)d_in[0], (const float*)d_in[1]);
    memann_mod<<<128, 256>>>(
        (const float*)d_in[2], (const float*)d_in[3],
        (const float*)d_in[4], (const float*)d_in[5],
        (const float*)d_in[6], (const float*)d_in[7],
        (const float*)d_in[8], (const float*)d_in[9],
        (float*)d_out);
    add_kernel<<<2048, 256>>>((float*)d_out);
}